// round 15
// baseline (speedup 1.0000x reference)
#include <cuda_runtime.h>
#include <cstdint>

// Chebyshev-KAN: out[b] = sum_d sum_{k=0..8} coeff[d*9+k] * T_k(x[b,d])
// x: (16384, 512) f32; coeff: (4608,) f32; out: (16384,) f32.
//
// R15: R10's two-kernel structure with the inter-kernel gap removed via
// Programmatic Dependent Launch. k1 = R10's exact partial engine (warp =
// 64-dim slice, monomial coeffs in 9 packed-f32x2 regs, TILE=4 row groups,
// depth-3 register pipeline, 9-shuffle fold tree, STG to scratch[row][8],
// no syncthreads) + cudaTriggerProgrammaticLaunchCompletion at the end.
// k2 = reduce (one row/thread, 2x LDG.128) entered via
// cudaGridDependencySynchronize, launched with programmatic stream
// serialization so its launch overlaps k1's drain.

#define DIM      512
#define NDEG     9
#define THREADS  256
#define TILE     4
#define NGROUPS  4096          // 16384 / 4
#define GRID1    592           // 148 SMs x 4 CTAs
#define NROWS    16384

typedef unsigned long long ull;

__device__ __align__(16) float g_partial[NROWS][8];   // 512 KB scratch

__device__ __forceinline__ ull pack2(float lo, float hi) {
    ull r; asm("mov.b64 %0, {%1, %2};" : "=l"(r) : "f"(lo), "f"(hi)); return r;
}
__device__ __forceinline__ void unpack2(ull v, float& lo, float& hi) {
    asm("mov.b64 {%0, %1}, %2;" : "=f"(lo), "=f"(hi) : "l"(v));
}
__device__ __forceinline__ ull fma2(ull a, ull b, ull c) {
    ull r; asm("fma.rn.f32x2 %0, %1, %2, %3;" : "=l"(r) : "l"(a), "l"(b), "l"(c)); return r;
}

// Chebyshev coeffs c[0..8] -> monomial coeffs a[0..8].
__device__ __forceinline__ void cheb2mono(const float* __restrict__ c, float* a) {
    a[8] = 128.0f * c[8];
    a[7] =  64.0f * c[7];
    a[6] = fmaf(-256.0f, c[8], 32.0f * c[6]);
    a[5] = fmaf(-112.0f, c[7], 16.0f * c[5]);
    a[4] = fmaf(160.0f, c[8], fmaf(-48.0f, c[6], 8.0f * c[4]));
    a[3] = fmaf( 56.0f, c[7], fmaf(-20.0f, c[5], 4.0f * c[3]));
    a[2] = fmaf(-32.0f, c[8], fmaf(18.0f, c[6], fmaf(-8.0f, c[4], 2.0f * c[2])));
    a[1] = fmaf( -7.0f, c[7], fmaf( 5.0f, c[5], fmaf(-3.0f, c[3], c[1])));
    a[0] = ((c[0] - c[2]) + (c[4] - c[6])) + c[8];
}

__device__ __forceinline__ void load_group(const float2* __restrict__ x2,
                                           int g, int col2, float2* xb) {
    const float2* p = x2 + (size_t)(TILE * g) * (DIM / 2) + col2;
    #pragma unroll
    for (int r = 0; r < TILE; ++r)
        xb[r] = p[r * (DIM / 2)];
}

// Compute 4 rows of this warp's slice s, fold, STG into g_partial[4g+rm][s].
__device__ __forceinline__ void do_group(const float2* xb, const ull* A,
                                         int s, int g, int lane) {
    float acc[TILE];
    #pragma unroll
    for (int r = 0; r < TILE; ++r) {
        ull xp = pack2(xb[r].x, xb[r].y);
        ull p = A[8];
        #pragma unroll
        for (int k = 7; k >= 0; --k) p = fma2(p, xp, A[k]);
        float lo, hi; unpack2(p, lo, hi);
        acc[r] = lo + hi;
    }
    // fold tree: 9 shuffles reduce 4 rows; lane bits (4,3) -> row
    float v0, v1;
    {
        float lo = acc[0] + __shfl_xor_sync(0xffffffffu, acc[0], 16);
        float hi = acc[1] + __shfl_xor_sync(0xffffffffu, acc[1], 16);
        v0 = (lane & 16) ? hi : lo;
        lo = acc[2] + __shfl_xor_sync(0xffffffffu, acc[2], 16);
        hi = acc[3] + __shfl_xor_sync(0xffffffffu, acc[3], 16);
        v1 = (lane & 16) ? hi : lo;
    }
    float u;
    {
        float lo = v0 + __shfl_xor_sync(0xffffffffu, v0, 8);
        float hi = v1 + __shfl_xor_sync(0xffffffffu, v1, 8);
        u = (lane & 8) ? hi : lo;
    }
    u += __shfl_xor_sync(0xffffffffu, u, 4);
    u += __shfl_xor_sync(0xffffffffu, u, 2);
    u += __shfl_xor_sync(0xffffffffu, u, 1);
    // lane 0 -> row 0, lane 8 -> row 2, lane 16 -> row 1, lane 24 -> row 3
    if ((lane & 7) == 0) {
        int rm = 2 * ((lane >> 3) & 1) + ((lane >> 4) & 1);
        g_partial[TILE * g + rm][s] = u;
    }
}

__global__ __launch_bounds__(THREADS, 4)
void kan_cheb_partial(const float* __restrict__ x,
                      const float* __restrict__ coeff)
{
    const int tid  = threadIdx.x;
    const int lane = tid & 31;
    const int s    = tid >> 5;            // slice 0..7 (fixed per warp)
    const int d0   = s * 64 + lane * 2;
    const int col2 = d0 >> 1;

    const float2* x2 = reinterpret_cast<const float2*>(x);

    // issue first two groups' loads BEFORE coefficient work (independent)
    int g = blockIdx.x;
    float2 xa[TILE], xb[TILE], xc[TILE];
    load_group(x2, g, col2, xa);
    if (g + GRID1 < NGROUPS) load_group(x2, g + GRID1, col2, xb);

    // coeff prologue: 18 consecutive floats -> monomial -> packed regs
    float cf[18];
    {
        const float2* c2 = reinterpret_cast<const float2*>(coeff + d0 * NDEG);
        #pragma unroll
        for (int i = 0; i < 9; ++i) { float2 v = c2[i]; cf[2*i] = v.x; cf[2*i+1] = v.y; }
    }
    ull A[9];
    {
        float t0[9], t1[9];
        cheb2mono(cf, t0); cheb2mono(cf + 9, t1);
        #pragma unroll
        for (int k = 0; k < 9; ++k) A[k] = pack2(t0[k], t1[k]);
    }

    // warp-autonomous grid-stride loop, depth-3 register pipeline
    for (;;) {
        int gp = g + 2 * GRID1;
        if (gp < NGROUPS) load_group(x2, gp, col2, xc);
        do_group(xa, A, s, g, lane);
        g += GRID1;
        if (g >= NGROUPS) break;

        gp = g + 2 * GRID1;
        if (gp < NGROUPS) load_group(x2, gp, col2, xa);
        do_group(xb, A, s, g, lane);
        g += GRID1;
        if (g >= NGROUPS) break;

        gp = g + 2 * GRID1;
        if (gp < NGROUPS) load_group(x2, gp, col2, xb);
        do_group(xc, A, s, g, lane);
        g += GRID1;
        if (g >= NGROUPS) break;
    }

    // allow the dependent reduce kernel to launch while this grid drains
    cudaTriggerProgrammaticLaunchCompletion();
}

// One thread per row: 8 contiguous partials via 2x LDG.128, sum, store.
__global__ __launch_bounds__(256)
void kan_cheb_reduce(float* __restrict__ out)
{
    // wait until the primary grid's scratch writes are visible
    cudaGridDependencySynchronize();
    const int row = blockIdx.x * 256 + threadIdx.x;
    const float4* p = reinterpret_cast<const float4*>(g_partial[row]);
    float4 a = p[0], b = p[1];
    out[row] = ((a.x + a.y) + (a.z + a.w)) + ((b.x + b.y) + (b.z + b.w));
}

extern "C" void kernel_launch(void* const* d_in, const int* in_sizes, int n_in,
                              void* d_out, int out_size)
{
    const float* x     = (const float*)d_in[0];
    const float* coeff = (const float*)d_in[1];
    // d_in[2] = degree (int32, fixed at 8) — baked in at compile time.
    float* out = (float*)d_out;

    kan_cheb_partial<<<GRID1, THREADS>>>(x, coeff);

    // dependent launch: overlap k2's launch with k1's drain (PDL)
    cudaLaunchConfig_t cfg = {};
    cfg.gridDim  = dim3(NROWS / 256);
    cfg.blockDim = dim3(256);
    cfg.dynamicSmemBytes = 0;
    cfg.stream = 0;
    cudaLaunchAttribute attr[1];
    attr[0].id = cudaLaunchAttributeProgrammaticStreamSerialization;
    attr[0].val.programmaticStreamSerializationAllowed = 1;
    cfg.attrs = attr;
    cfg.numAttrs = 1;
    cudaLaunchKernelEx(&cfg, kan_cheb_reduce, out);
}

// round 16
// speedup vs baseline: 1.1662x; 1.1662x over previous
#include <cuda_runtime.h>
#include <cstdint>

// Chebyshev-KAN: out[b] = sum_d sum_{k=0..8} coeff[d*9+k] * T_k(x[b,d])
// x: (16384, 512) f32; coeff: (4608,) f32; out: (16384,) f32.
//
// R16: tail-balance reshape of the champion fused engine. 512-thread CTAs,
// grid 296 (2 CTAs/SM, single wave). 16 warps = 8 dim-slices x 2 row-halves:
// warp (h,s) handles rows [4h,4h+4) of each 8-row group for slice s
// (monomial coeffs in 9 packed-f32x2 regs, depth-3 register pipeline,
// 9-shuffle fold tree). Last grid-stride iteration runs 272/296 CTAs (92%
// utilization, vs 62% at grid 592) -- recovers the ~0.5us tail.

#define DIM      512
#define NDEG     9
#define THREADS  512
#define GTILE    8             // rows per CTA group
#define WTILE    4             // rows per warp
#define NGROUPS  2048          // 16384 / 8
#define GRID1    296           // 148 SMs x 2 CTAs, single wave
#define MAXIT    7             // ceil(2048/296)
#define SSTRIDE  9

typedef unsigned long long ull;

__device__ __forceinline__ ull pack2(float lo, float hi) {
    ull r; asm("mov.b64 %0, {%1, %2};" : "=l"(r) : "f"(lo), "f"(hi)); return r;
}
__device__ __forceinline__ void unpack2(ull v, float& lo, float& hi) {
    asm("mov.b64 {%0, %1}, %2;" : "=f"(lo), "=f"(hi) : "l"(v));
}
__device__ __forceinline__ ull fma2(ull a, ull b, ull c) {
    ull r; asm("fma.rn.f32x2 %0, %1, %2, %3;" : "=l"(r) : "l"(a), "l"(b), "l"(c)); return r;
}

// Chebyshev coeffs c[0..8] -> monomial coeffs a[0..8].
__device__ __forceinline__ void cheb2mono(const float* __restrict__ c, float* a) {
    a[8] = 128.0f * c[8];
    a[7] =  64.0f * c[7];
    a[6] = fmaf(-256.0f, c[8], 32.0f * c[6]);
    a[5] = fmaf(-112.0f, c[7], 16.0f * c[5]);
    a[4] = fmaf(160.0f, c[8], fmaf(-48.0f, c[6], 8.0f * c[4]));
    a[3] = fmaf( 56.0f, c[7], fmaf(-20.0f, c[5], 4.0f * c[3]));
    a[2] = fmaf(-32.0f, c[8], fmaf(18.0f, c[6], fmaf(-8.0f, c[4], 2.0f * c[2])));
    a[1] = fmaf( -7.0f, c[7], fmaf( 5.0f, c[5], fmaf(-3.0f, c[3], c[1])));
    a[0] = ((c[0] - c[2]) + (c[4] - c[6])) + c[8];
}

// Load this warp's 4 rows (rows 4h..4h+3 of group g) of its 64-dim slice.
__device__ __forceinline__ void load_group(const float2* __restrict__ x2,
                                           int g, int rowoff, int col2,
                                           float2* xb) {
    const float2* p = x2 + (size_t)(GTILE * g + rowoff) * (DIM / 2) + col2;
    #pragma unroll
    for (int r = 0; r < WTILE; ++r)
        xb[r] = p[r * (DIM / 2)];
}

// Compute 4 rows of slice s, fold, store smem partials for local rows.
__device__ __forceinline__ void do_group(const float2* xb, const ull* A,
                                         float* __restrict__ s_part,
                                         int s, int lrow0, int lane) {
    float acc[WTILE];
    #pragma unroll
    for (int r = 0; r < WTILE; ++r) {
        ull xp = pack2(xb[r].x, xb[r].y);
        ull p = A[8];
        #pragma unroll
        for (int k = 7; k >= 0; --k) p = fma2(p, xp, A[k]);
        float lo, hi; unpack2(p, lo, hi);
        acc[r] = lo + hi;
    }
    // fold tree: 9 shuffles reduce 4 rows; lane bits (4,3) -> row
    float v0, v1;
    {
        float lo = acc[0] + __shfl_xor_sync(0xffffffffu, acc[0], 16);
        float hi = acc[1] + __shfl_xor_sync(0xffffffffu, acc[1], 16);
        v0 = (lane & 16) ? hi : lo;
        lo = acc[2] + __shfl_xor_sync(0xffffffffu, acc[2], 16);
        hi = acc[3] + __shfl_xor_sync(0xffffffffu, acc[3], 16);
        v1 = (lane & 16) ? hi : lo;
    }
    float u;
    {
        float lo = v0 + __shfl_xor_sync(0xffffffffu, v0, 8);
        float hi = v1 + __shfl_xor_sync(0xffffffffu, v1, 8);
        u = (lane & 8) ? hi : lo;
    }
    u += __shfl_xor_sync(0xffffffffu, u, 4);
    u += __shfl_xor_sync(0xffffffffu, u, 2);
    u += __shfl_xor_sync(0xffffffffu, u, 1);
    // lane 0 -> row 0, lane 8 -> row 2, lane 16 -> row 1, lane 24 -> row 3
    if ((lane & 7) == 0) {
        int rm = 2 * ((lane >> 3) & 1) + ((lane >> 4) & 1);
        s_part[(lrow0 + rm) * SSTRIDE + s] = u;
    }
}

__global__ __launch_bounds__(THREADS, 2)
void kan_cheb_kernel(const float* __restrict__ x,
                     const float* __restrict__ coeff,
                     float* __restrict__ out)
{
    __shared__ float s_part[MAXIT * GTILE * SSTRIDE];   // 7*8*9*4 = 2016 B

    const int tid  = threadIdx.x;
    const int lane = tid & 31;
    const int w    = tid >> 5;            // warp 0..15
    const int s    = w & 7;               // dim slice 0..7
    const int h    = w >> 3;              // row half 0/1
    const int rowoff = h * WTILE;
    const int d0   = s * 64 + lane * 2;
    const int col2 = d0 >> 1;
    const int bid  = blockIdx.x;

    const float2* x2 = reinterpret_cast<const float2*>(x);

    // issue first two groups' loads BEFORE coefficient work (independent)
    int g = bid;
    float2 xa[WTILE], xb[WTILE], xc[WTILE];
    load_group(x2, g, rowoff, col2, xa);
    if (g + GRID1 < NGROUPS) load_group(x2, g + GRID1, rowoff, col2, xb);

    // coeff prologue: 18 consecutive floats -> monomial -> packed regs
    float cf[18];
    {
        const float2* c2 = reinterpret_cast<const float2*>(coeff + d0 * NDEG);
        #pragma unroll
        for (int i = 0; i < 9; ++i) { float2 v = c2[i]; cf[2*i] = v.x; cf[2*i+1] = v.y; }
    }
    ull A[9];
    {
        float t0[9], t1[9];
        cheb2mono(cf, t0); cheb2mono(cf + 9, t1);
        #pragma unroll
        for (int k = 0; k < 9; ++k) A[k] = pack2(t0[k], t1[k]);
    }

    // grid-stride loop, depth-3 register pipeline
    int slot = 0;
    for (;;) {
        int gp = g + 2 * GRID1;
        if (gp < NGROUPS) load_group(x2, gp, rowoff, col2, xc);
        do_group(xa, A, s_part, s, slot * GTILE + rowoff, lane);
        g += GRID1; ++slot;
        if (g >= NGROUPS) break;

        gp = g + 2 * GRID1;
        if (gp < NGROUPS) load_group(x2, gp, rowoff, col2, xa);
        do_group(xb, A, s_part, s, slot * GTILE + rowoff, lane);
        g += GRID1; ++slot;
        if (g >= NGROUPS) break;

        gp = g + 2 * GRID1;
        if (gp < NGROUPS) load_group(x2, gp, rowoff, col2, xb);
        do_group(xc, A, s_part, s, slot * GTILE + rowoff, lane);
        g += GRID1; ++slot;
        if (g >= NGROUPS) break;
    }

    // in-CTA finalize: one sync; thread (it,rm) sums 8 slice partials
    __syncthreads();
    if (tid < MAXIT * GTILE) {
        const int it = tid >> 3;          // iteration slot
        const int rm = tid & 7;           // row within group
        const int gg = bid + it * GRID1;
        if (gg < NGROUPS) {
            const float* p = &s_part[tid * SSTRIDE];
            float r = ((p[0] + p[1]) + (p[2] + p[3])) + ((p[4] + p[5]) + (p[6] + p[7]));
            out[gg * GTILE + rm] = r;
        }
    }
}

extern "C" void kernel_launch(void* const* d_in, const int* in_sizes, int n_in,
                              void* d_out, int out_size)
{
    const float* x     = (const float*)d_in[0];
    const float* coeff = (const float*)d_in[1];
    // d_in[2] = degree (int32, fixed at 8) — baked in at compile time.
    float* out = (float*)d_out;

    kan_cheb_kernel<<<GRID1, THREADS>>>(x, coeff, out);
}